// round 6
// baseline (speedup 1.0000x reference)
#include <cuda_runtime.h>

// context[b,d] = sum_t keys[b,t,d]   (softmax over size-1 axis == 1; rest dead)
// R6: single launch. Contiguous-streaming slab blocks (proven 41.3us reader)
// + fused last-block-per-batch finalize with ONE fence per block (cumulative
// fence: syncthreads -> tid0 threadfence -> atomic), not one per thread (R4's
// mistake). Partials stored [b][col][slab] so finalize loads are contiguous.

#define B_SZ   32
#define D4     128          // 512 floats = 128 float4 per row
#define NSLAB  19           // 32*19 = 608 blocks = 2 * (152 SMs * 2 blocks)
#define NGRP   512          // 4096 rows / 8 rows-per-iteration
#define GPS    27           // groups per slab (last slab gets 512-18*27 = 26)

__device__ float4 g_partial[B_SZ * D4 * NSLAB];   // 1.2 MB, [b][col][s]
__device__ int    g_cnt[B_SZ];                    // zero-init; reset by finalizer

__global__ __launch_bounds__(1024, 2)
void keys_sum_fused_kernel(const float4* __restrict__ keys4,
                           float4* __restrict__ out4) {
    const int bid = blockIdx.x;            // 0..607
    const int b   = bid / NSLAB;
    const int s   = bid - b * NSLAB;
    const int g0  = s * GPS;
    const int ng  = (s == NSLAB - 1) ? (NGRP - g0) : GPS;   // 27 or 26
    const int tid = threadIdx.x;

    // ---- stream: 16 KB/iter fully contiguous; column = tid & 127 ----
    const float4* p = keys4 + b * (4096 * D4) + g0 * 1024 + tid;

    float4 acc = make_float4(0.f, 0.f, 0.f, 0.f);
    #pragma unroll 4
    for (int i = 0; i < ng; ++i) {
        float4 v = __ldcs(p + i * 1024);
        acc.x += v.x; acc.y += v.y; acc.z += v.z; acc.w += v.w;
    }

    __shared__ float4 sm[1024];
    sm[tid] = acc;
    __syncthreads();
    if (tid < 512) {
        float4 o = sm[tid + 512];
        sm[tid].x += o.x; sm[tid].y += o.y; sm[tid].z += o.z; sm[tid].w += o.w;
    }
    __syncthreads();
    if (tid < 256) {
        float4 o = sm[tid + 256];
        sm[tid].x += o.x; sm[tid].y += o.y; sm[tid].z += o.z; sm[tid].w += o.w;
    }
    __syncthreads();
    if (tid < 128) {
        float4 m = sm[tid];
        float4 o = sm[tid + 128];
        m.x += o.x; m.y += o.y; m.z += o.z; m.w += o.w;
        g_partial[(b * D4 + tid) * NSLAB + s] = m;   // transposed layout
    }
    __syncthreads();   // partial STGs ordered before tid0's fence (fence.cta)

    // ---- publish: ONE release fence + atomic per block ----
    __shared__ int is_last;
    if (tid == 0) {
        __threadfence();                   // release (cumulative over block)
        is_last = (atomicAdd(&g_cnt[b], 1) == NSLAB - 1);
    }
    __syncthreads();
    if (!is_last) return;
    if (tid == 0) __threadfence();         // acquire other blocks' partials
    __syncthreads();

    // ---- finalize: 128 cols x 8 slab-groups; loads contiguous per col ----
    const int col = tid & 127;
    const int q   = tid >> 7;              // 0..7
    float4 a = make_float4(0.f, 0.f, 0.f, 0.f);
    #pragma unroll
    for (int ss = q; ss < NSLAB; ss += 8) {
        float4 v = g_partial[(b * D4 + col) * NSLAB + ss];
        a.x += v.x; a.y += v.y; a.z += v.z; a.w += v.w;
    }
    sm[tid] = a;
    __syncthreads();
    if (tid < 512) {
        float4 o = sm[tid + 512];
        sm[tid].x += o.x; sm[tid].y += o.y; sm[tid].z += o.z; sm[tid].w += o.w;
    }
    __syncthreads();
    if (tid < 256) {
        float4 o = sm[tid + 256];
        sm[tid].x += o.x; sm[tid].y += o.y; sm[tid].z += o.z; sm[tid].w += o.w;
    }
    __syncthreads();
    if (tid < 128) {
        float4 m = sm[tid];
        float4 o = sm[tid + 128];
        m.x += o.x; m.y += o.y; m.z += o.z; m.w += o.w;
        out4[b * D4 + tid] = m;
    }
    if (tid == 0) g_cnt[b] = 0;            // reset for next graph replay
}

extern "C" void kernel_launch(void* const* d_in, const int* in_sizes, int n_in,
                              void* d_out, int out_size) {
    // metadata order: query[0], keys[1], Ws[2], Wh[3], W[4]; only keys is live.
    const float4* keys4 = (const float4*)d_in[1];
    float4* out4 = (float4*)d_out;

    keys_sum_fused_kernel<<<B_SZ * NSLAB, 1024>>>(keys4, out4);
}

// round 7
// speedup vs baseline: 1.2740x; 1.2740x over previous
#include <cuda_runtime.h>

// context[b,d] = sum_t keys[b,t,d]   (softmax over size-1 axis == 1; rest dead)
// R7 = R2 (champion: direct-output, no inter-block sync, 256x1024) +
// prefetch.global.L2 running 8 rows ahead. launch_bounds(1024,2) caps regs at
// 32 -> demand-load MLP ~6/thread; prefetch adds DRAM-side parallelism with
// zero register/scoreboard cost, turning demand LDGs into L2 hits.

#define B_SZ 32
#define T_LEN 4096
#define D_DIM 512           // floats
#define D4 (D_DIM / 4)      // 128 float4 per row
#define PF 8                // prefetch distance (rows)

// Grid: x = D-chunk (8 chunks of 16 float4 = 64 floats), y = batch (32).
// Block: 1024 threads = 16 float4-columns x 64 T-partitions.
// Each thread streams 64 rows of one float4 column; smem tree-reduce partitions.
__global__ __launch_bounds__(1024, 2)
void keys_sum_kernel(const float4* __restrict__ keys4, float4* __restrict__ out4) {
    const int tid   = threadIdx.x;
    const int col   = tid & 15;          // 0..15 within chunk
    const int part  = tid >> 4;          // 0..63 T-partition
    const int chunk = blockIdx.x;        // 0..7
    const int b     = blockIdx.y;        // 0..31

    const int col4 = chunk * 16 + col;   // global float4 column 0..127
    const float4* p = keys4 + (b * T_LEN + part * 64) * D4 + col4;

    float4 acc = make_float4(0.f, 0.f, 0.f, 0.f);

    // main loop: prefetch PF rows ahead, demand-load current row
    #pragma unroll 8
    for (int i = 0; i < 64 - PF; ++i) {
        asm volatile("prefetch.global.L2 [%0];" :: "l"(p + (i + PF) * D4));
        float4 v = __ldcs(p + i * D4);
        acc.x += v.x; acc.y += v.y; acc.z += v.z; acc.w += v.w;
    }
    // tail: last PF rows, already prefetched
    #pragma unroll
    for (int i = 64 - PF; i < 64; ++i) {
        float4 v = __ldcs(p + i * D4);
        acc.x += v.x; acc.y += v.y; acc.z += v.z; acc.w += v.w;
    }

    __shared__ float4 sm[1024];
    sm[tid] = acc;
    __syncthreads();

    // reduce across the 64 T-partitions (stride-16 layout keeps per-col sums)
    #pragma unroll
    for (int s = 512; s >= 16; s >>= 1) {
        if (tid < s) {
            float4 o = sm[tid + s];
            float4 m = sm[tid];
            m.x += o.x; m.y += o.y; m.z += o.z; m.w += o.w;
            sm[tid] = m;
        }
        __syncthreads();
    }

    if (tid < 16) {
        out4[b * D4 + chunk * 16 + tid] = sm[tid];
    }
}

extern "C" void kernel_launch(void* const* d_in, const int* in_sizes, int n_in,
                              void* d_out, int out_size) {
    // metadata order: query[0], keys[1], Ws[2], Wh[3], W[4]; only keys is live.
    const float* keys = (const float*)d_in[1];
    float* out = (float*)d_out;

    dim3 grid(D4 / 16, B_SZ);   // (8, 32) = 256 blocks, one resident wave
    keys_sum_kernel<<<grid, 1024>>>((const float4*)keys, (float4*)out);
}